// round 13
// baseline (speedup 1.0000x reference)
#include <cuda_runtime.h>
#include <cuda_fp16.h>
#include <cstdint>
#include <cstddef>

// ---------------- problem dims ----------------
#define BATCH 2048
#define SEQ   64
#define CH    1024
#define NH    16
#define DHD   64
#define MROWS (BATCH*SEQ)   // 131072
#define KD    1024
#define NQKV  3072
#define NBH   (BATCH*NH)    // 32768

// ---------------- GEMM tiling ----------------
#define BM   128
#define BN   128
#define BK   64
#define PIPE 3
#define NSTAGE (KD/BK)          // 16
#define GT   128                // 4 warps, warp tile 64x64
#define ASTR (BK + 8)           // 72
#define BSTR (BN + 8)           // 136
#define A_BYTES (BM * ASTR * 2) // 18432
#define B_BYTES (BK * BSTR * 2) // 17408
#define STAGE_BYTES (A_BYTES + B_BYTES) // 35840
#define SMEM_DYN (PIPE * STAGE_BYTES)   // 107520

// ---------------- attention tiling ----------------
#define QKV_STR 72                       // padded row stride (halfs)
#define TILE_H  (SEQ * QKV_STR)          // 4608 halfs per tile
#define BUF_H   (3 * TILE_H)             // 13824 halfs per buffer
#define ATT_SMEM (2 * BUF_H * 2)         // 55296 bytes
#define ATT_G   444                      // persistent grid (3 per SM x 148)

// ---------------- scratch ----------------
__device__ __align__(256) __half g_x16[(size_t)MROWS * KD];
__device__ __align__(256) __half g_q[(size_t)BATCH * NH * SEQ * DHD];   // [B,H,L,dh]
__device__ __align__(256) __half g_k[(size_t)BATCH * NH * SEQ * DHD];
__device__ __align__(256) __half g_v[(size_t)BATCH * NH * SEQ * DHD];
__device__ __align__(256) __half g_o[(size_t)MROWS * CH];               // [B*L, C]
__device__ __align__(256) __half g_wqkv16[(size_t)KD * NQKV];           // [K,N] row-major
__device__ __align__(256) __half g_wout16[(size_t)KD * CH];             // [K,N] row-major
__device__ __align__(256) float  g_bias[NH * SEQ * SEQ];                // [H,64,64]

// ---------------- helpers ----------------
__device__ __forceinline__ uint32_t smem_u32(const void* p) {
    return (uint32_t)__cvta_generic_to_shared(p);
}
__device__ __forceinline__ void cp16(uint32_t s, const void* g) {
    asm volatile("cp.async.cg.shared.global [%0], [%1], 16;" :: "r"(s), "l"(g) : "memory");
}
__device__ __forceinline__ void ldsm_x4(uint32_t& r0, uint32_t& r1, uint32_t& r2, uint32_t& r3, uint32_t a) {
    asm volatile("ldmatrix.sync.aligned.m8n8.x4.shared.b16 {%0,%1,%2,%3}, [%4];"
                 : "=r"(r0), "=r"(r1), "=r"(r2), "=r"(r3) : "r"(a));
}
__device__ __forceinline__ void ldsm_x4t(uint32_t& r0, uint32_t& r1, uint32_t& r2, uint32_t& r3, uint32_t a) {
    asm volatile("ldmatrix.sync.aligned.m8n8.x4.trans.shared.b16 {%0,%1,%2,%3}, [%4];"
                 : "=r"(r0), "=r"(r1), "=r"(r2), "=r"(r3) : "r"(a));
}
__device__ __forceinline__ void mma_16816(float* c, const uint32_t* a, const uint32_t* b) {
    asm volatile("mma.sync.aligned.m16n8k16.row.col.f32.f16.f16.f32 "
                 "{%0,%1,%2,%3}, {%4,%5,%6,%7}, {%8,%9}, {%0,%1,%2,%3};"
                 : "+f"(c[0]), "+f"(c[1]), "+f"(c[2]), "+f"(c[3])
                 : "r"(a[0]), "r"(a[1]), "r"(a[2]), "r"(a[3]), "r"(b[0]), "r"(b[1]));
}
__device__ __forceinline__ uint32_t h2_as_u32(__half2 h) {
    return *reinterpret_cast<uint32_t*>(&h);
}

// ---------------- prep kernels (f32 -> f16, vectorized) ----------------
__global__ void conv_x(const float* __restrict__ x) {
    size_t step = (size_t)gridDim.x * blockDim.x * 4;
    size_t total = (size_t)MROWS * KD;
    for (size_t i = ((size_t)blockIdx.x * blockDim.x + threadIdx.x) * 4; i < total; i += step) {
        float4 v = *(const float4*)(x + i);
        uint2 u = make_uint2(h2_as_u32(__floats2half2_rn(v.x, v.y)),
                             h2_as_u32(__floats2half2_rn(v.z, v.w)));
        *(uint2*)(g_x16 + i) = u;
    }
}
// fused: weights f32->f16 + bias table build
__global__ void conv_w_bias(const float* __restrict__ wqkv, const float* __restrict__ wout,
                            const float* __restrict__ rel) {
    size_t t1 = (size_t)KD * NQKV;
    size_t total = t1 + (size_t)KD * CH;
    size_t step = (size_t)gridDim.x * blockDim.x * 4;
    for (size_t i = ((size_t)blockIdx.x * blockDim.x + threadIdx.x) * 4; i < total; i += step) {
        const float* src = (i < t1) ? (wqkv + i) : (wout + (i - t1));
        __half* dst = (i < t1) ? (g_wqkv16 + i) : (g_wout16 + (i - t1));
        float4 v = *(const float4*)src;
        uint2 u = make_uint2(h2_as_u32(__floats2half2_rn(v.x, v.y)),
                             h2_as_u32(__floats2half2_rn(v.z, v.w)));
        *(uint2*)dst = u;
    }
    int gi = blockIdx.x * blockDim.x + threadIdx.x;
    if (gi < NH * SEQ * SEQ) {
        int h = gi >> 12, q = (gi >> 6) & 63, k = gi & 63;
        int dr = (q >> 3) - (k >> 3) + 7;
        int dc = (q & 7) - (k & 7) + 7;
        g_bias[gi] = rel[(dr * 15 + dc) * NH + h];
    }
}

// ---------------- fp16 HMMA GEMM: 4 warps, warp tile 64x64, cp.async 3-stage ----------------
template<int EPI>
__global__ __launch_bounds__(GT, 2)
void gemm_hmma(const float* __restrict__ bvec, float* __restrict__ outF)
{
    extern __shared__ __align__(16) char dynsm[];
    constexpr int ND = (EPI == 0) ? NQKV : CH;
    const __half* __restrict__ A  = (EPI == 0) ? g_x16 : g_o;
    const __half* __restrict__ Bw = (EPI == 0) ? g_wqkv16 : g_wout16;

    const int tid = threadIdx.x;
    const int w = tid >> 5, lane = tid & 31;
    const int wm = w >> 1, wn = w & 1;     // 2x2 warps, warp tile 64x64
    const int m0 = blockIdx.y * BM;
    const int n0 = blockIdx.x * BN;

    float acc[4][8][4];
    #pragma unroll
    for (int mi = 0; mi < 4; mi++)
        #pragma unroll
        for (int j = 0; j < 8; j++)
            #pragma unroll
            for (int q = 0; q < 4; q++) acc[mi][j][q] = 0.f;

    const uint32_t sb = smem_u32(dynsm);

    const int arow = tid >> 3, ac = tid & 7;
    const int brow = tid >> 4, bc = tid & 15;

    auto load_stage = [&](int s) {
        uint32_t base = sb + (uint32_t)(s % PIPE) * STAGE_BYTES;
        const __half* ag = A + (size_t)m0 * KD + s * BK;
        const __half* bg = Bw + (size_t)(s * BK) * ND + n0;
        #pragma unroll
        for (int i = 0; i < 8; i++) {
            int r = arow + i * 16;
            cp16(base + (uint32_t)(r * ASTR + ac * 8) * 2, ag + (size_t)r * KD + ac * 8);
        }
        #pragma unroll
        for (int i = 0; i < 8; i++) {
            int r = brow + i * 8;
            cp16(base + A_BYTES + (uint32_t)(r * BSTR + bc * 8) * 2, bg + (size_t)r * ND + bc * 8);
        }
        asm volatile("cp.async.commit_group;" ::: "memory");
    };

    load_stage(0);
    load_stage(1);

    const int a_row_sel = wm * 64 + (lane & 15);
    const int a_col_sel = (lane >> 4) * 8;
    const int b_mi2 = lane >> 3, b_r = lane & 7;
    const int b_row_sel = (b_mi2 & 1) * 8 + b_r;
    const int b_col_sel = wn * 64 + (b_mi2 >> 1) * 8;

    uint32_t afr[2][4][4];
    uint32_t bfr[2][8][2];

    auto load_frags = [&](int buf, uint32_t aBase, uint32_t bBase, int kk) {
        #pragma unroll
        for (int mi = 0; mi < 4; mi++) {
            uint32_t ad = aBase + (uint32_t)((a_row_sel + mi * 16) * ASTR + kk * 16 + a_col_sel) * 2;
            ldsm_x4(afr[buf][mi][0], afr[buf][mi][1], afr[buf][mi][2], afr[buf][mi][3], ad);
        }
        #pragma unroll
        for (int j2 = 0; j2 < 4; j2++) {
            uint32_t bd = bBase + (uint32_t)((kk * 16 + b_row_sel) * BSTR + b_col_sel + j2 * 16) * 2;
            uint32_t r0, r1, r2, r3;
            ldsm_x4t(r0, r1, r2, r3, bd);
            bfr[buf][2 * j2][0] = r0;     bfr[buf][2 * j2][1] = r1;
            bfr[buf][2 * j2 + 1][0] = r2; bfr[buf][2 * j2 + 1][1] = r3;
        }
    };

    for (int kt = 0; kt < NSTAGE; kt++) {
        if (kt + 1 < NSTAGE) asm volatile("cp.async.wait_group 1;" ::: "memory");
        else                 asm volatile("cp.async.wait_group 0;" ::: "memory");
        __syncthreads();
        if (kt + 2 < NSTAGE) load_stage(kt + 2);

        uint32_t aBase = sb + (uint32_t)(kt % PIPE) * STAGE_BYTES;
        uint32_t bBase = aBase + A_BYTES;

        load_frags(0, aBase, bBase, 0);
        #pragma unroll
        for (int kk = 0; kk < 4; kk++) {
            int cur = kk & 1;
            if (kk < 3) load_frags(cur ^ 1, aBase, bBase, kk + 1);
            #pragma unroll
            for (int mi = 0; mi < 4; mi++)
                #pragma unroll
                for (int j = 0; j < 8; j++)
                    mma_16816(acc[mi][j], afr[cur][mi], bfr[cur][j]);
        }
    }

    // ---------------- epilogue ----------------
    const int rbase = m0 + wm * 64;
    const int cbase = n0 + wn * 64;
    if constexpr (EPI == 0) {
        int part = cbase >> 10;
        int h = (cbase >> 6) & (NH - 1);
        __half* dst = (part == 0) ? g_q : (part == 1) ? g_k : g_v;
        #pragma unroll
        for (int mi = 0; mi < 4; mi++) {
            int row0 = rbase + mi * 16 + (lane >> 2);
            int row1 = row0 + 8;
            size_t base0 = ((size_t)((row0 >> 6) * NH + h)) * 4096 + (size_t)(row0 & 63) * 64;
            size_t base1 = ((size_t)((row1 >> 6) * NH + h)) * 4096 + (size_t)(row1 & 63) * 64;
            #pragma unroll
            for (int j = 0; j < 8; j++) {
                int d = j * 8 + 2 * (lane & 3);
                *(__half2*)&dst[base0 + d] = __floats2half2_rn(acc[mi][j][0], acc[mi][j][1]);
                *(__half2*)&dst[base1 + d] = __floats2half2_rn(acc[mi][j][2], acc[mi][j][3]);
            }
        }
    } else {
        #pragma unroll
        for (int mi = 0; mi < 4; mi++) {
            int row0 = rbase + mi * 16 + (lane >> 2);
            int row1 = row0 + 8;
            #pragma unroll
            for (int j = 0; j < 8; j++) {
                int col = cbase + j * 8 + 2 * (lane & 3);
                float2 bb = *(const float2*)&bvec[col];
                float2 v0 = make_float2(acc[mi][j][0] + bb.x, acc[mi][j][1] + bb.y);
                float2 v1 = make_float2(acc[mi][j][2] + bb.x, acc[mi][j][3] + bb.y);
                *(float2*)&outF[(size_t)row0 * CH + col] = v0;
                *(float2*)&outF[(size_t)row1 * CH + col] = v1;
            }
        }
    }
}

// ---------------- persistent attention: double-buffered cp.async over (b,h) ----------------
// per buffer (halfs): Q at +0, K at +TILE_H, V at +2*TILE_H; row stride QKV_STR
__global__ __launch_bounds__(128, 3)
void attn_kernel()
{
    extern __shared__ __align__(16) __half attsm[];
    const int tid = threadIdx.x;
    const int w = tid >> 5, lane = tid & 31;
    const uint32_t sb = smem_u32(attsm);

    auto load_bh = [&](int buf, int bh) {
        uint32_t base = sb + (uint32_t)buf * BUF_H * 2;
        size_t tb = (size_t)bh * (SEQ * DHD);
        #pragma unroll
        for (int t = 0; t < 3; t++) {
            const __half* src = (t == 0) ? g_q : (t == 1) ? g_k : g_v;
            uint32_t tbase = base + (uint32_t)t * TILE_H * 2;
            #pragma unroll
            for (int i = 0; i < 4; i++) {
                int u = tid + i * 128;
                int row = u >> 3, c8 = (u & 7) * 8;
                cp16(tbase + (uint32_t)(row * QKV_STR + c8) * 2, src + tb + row * DHD + c8);
            }
        }
        asm volatile("cp.async.commit_group;" ::: "memory");
    };

    const int m0 = w * 16;
    const int q0 = m0 + (lane >> 2);
    const int q1 = q0 + 8;

    int i0 = blockIdx.x;
    if (i0 < NBH) load_bh(0, i0);

    int buf = 0;
    for (int i = i0; i < NBH; i += ATT_G) {
        int inext = i + ATT_G;
        if (inext < NBH) {
            load_bh(buf ^ 1, inext);
            asm volatile("cp.async.wait_group 1;" ::: "memory");
        } else {
            asm volatile("cp.async.wait_group 0;" ::: "memory");
        }

        const int b = i >> 4;
        const int h = i & (NH - 1);
        const float* bg = g_bias + h * (SEQ * SEQ);

        // init score accumulators with 8*bias (exact power-of-2 scaling)
        float sc[8][4];
        #pragma unroll
        for (int j = 0; j < 8; j++) {
            int col = j * 8 + 2 * (lane & 3);
            float2 t0 = __ldg((const float2*)(bg + q0 * SEQ + col));
            float2 t1 = __ldg((const float2*)(bg + q1 * SEQ + col));
            sc[j][0] = t0.x * 8.f; sc[j][1] = t0.y * 8.f;
            sc[j][2] = t1.x * 8.f; sc[j][3] = t1.y * 8.f;
        }

        __syncthreads();   // buffer `buf` data visible to all warps

        const uint32_t bQ = sb + (uint32_t)buf * BUF_H * 2;
        const uint32_t bK = bQ + TILE_H * 2;
        const uint32_t bV = bK + TILE_H * 2;

        // S = Q @ K^T (+ 8*bias preloaded)
        #pragma unroll
        for (int kk = 0; kk < 4; kk++) {
            uint32_t a[4];
            uint32_t ad = bQ + (uint32_t)((m0 + (lane & 15)) * QKV_STR + kk * 16 + (lane >> 4) * 8) * 2;
            ldsm_x4(a[0], a[1], a[2], a[3], ad);
            uint32_t kf[8][2];
            #pragma unroll
            for (int j2 = 0; j2 < 4; j2++) {
                int mi = lane >> 3, r = lane & 7;
                uint32_t kad = bK + (uint32_t)((j2 * 16 + (mi >> 1) * 8 + r) * QKV_STR + kk * 16 + (mi & 1) * 8) * 2;
                uint32_t r0, r1, r2, r3;
                ldsm_x4(r0, r1, r2, r3, kad);
                kf[2 * j2][0] = r0;     kf[2 * j2][1] = r1;
                kf[2 * j2 + 1][0] = r2; kf[2 * j2 + 1][1] = r3;
            }
            #pragma unroll
            for (int j = 0; j < 8; j++) mma_16816(sc[j], a, kf[j]);
        }

        // softmax (scale by 0.125 exactly)
        float mx0 = -1e30f, mx1 = -1e30f;
        #pragma unroll
        for (int j = 0; j < 8; j++) {
            sc[j][0] *= 0.125f; sc[j][1] *= 0.125f;
            sc[j][2] *= 0.125f; sc[j][3] *= 0.125f;
            mx0 = fmaxf(mx0, fmaxf(sc[j][0], sc[j][1]));
            mx1 = fmaxf(mx1, fmaxf(sc[j][2], sc[j][3]));
        }
        mx0 = fmaxf(mx0, __shfl_xor_sync(0xffffffffu, mx0, 1));
        mx0 = fmaxf(mx0, __shfl_xor_sync(0xffffffffu, mx0, 2));
        mx1 = fmaxf(mx1, __shfl_xor_sync(0xffffffffu, mx1, 1));
        mx1 = fmaxf(mx1, __shfl_xor_sync(0xffffffffu, mx1, 2));
        float s0 = 0.f, s1 = 0.f;
        #pragma unroll
        for (int j = 0; j < 8; j++) {
            sc[j][0] = __expf(sc[j][0] - mx0);
            sc[j][1] = __expf(sc[j][1] - mx0);
            sc[j][2] = __expf(sc[j][2] - mx1);
            sc[j][3] = __expf(sc[j][3] - mx1);
            s0 += sc[j][0] + sc[j][1];
            s1 += sc[j][2] + sc[j][3];
        }
        s0 += __shfl_xor_sync(0xffffffffu, s0, 1);
        s0 += __shfl_xor_sync(0xffffffffu, s0, 2);
        s1 += __shfl_xor_sync(0xffffffffu, s1, 1);
        s1 += __shfl_xor_sync(0xffffffffu, s1, 2);
        float inv0 = 1.f / s0;
        float inv1 = 1.f / s1;

        uint32_t pf[8][2];
        #pragma unroll
        for (int j = 0; j < 8; j++) {
            pf[j][0] = h2_as_u32(__floats2half2_rn(sc[j][0] * inv0, sc[j][1] * inv0));
            pf[j][1] = h2_as_u32(__floats2half2_rn(sc[j][2] * inv1, sc[j][3] * inv1));
        }

        // O = P @ V
        float oc[8][4];
        #pragma unroll
        for (int j = 0; j < 8; j++)
            #pragma unroll
            for (int q = 0; q < 4; q++) oc[j][q] = 0.f;

        #pragma unroll
        for (int kk2 = 0; kk2 < 4; kk2++) {
            uint32_t a2[4] = { pf[2 * kk2][0], pf[2 * kk2][1], pf[2 * kk2 + 1][0], pf[2 * kk2 + 1][1] };
            uint32_t vf[8][2];
            #pragma unroll
            for (int dj2 = 0; dj2 < 4; dj2++) {
                int mi = lane >> 3, r = lane & 7;
                uint32_t vad = bV + (uint32_t)((kk2 * 16 + (mi & 1) * 8 + r) * QKV_STR + dj2 * 16 + (mi >> 1) * 8) * 2;
                uint32_t r0, r1, r2, r3;
                ldsm_x4t(r0, r1, r2, r3, vad);
                vf[2 * dj2][0] = r0;     vf[2 * dj2][1] = r1;
                vf[2 * dj2 + 1][0] = r2; vf[2 * dj2 + 1][1] = r3;
            }
            #pragma unroll
            for (int j = 0; j < 8; j++) mma_16816(oc[j], a2, vf[j]);
        }

        // store O as [B*L, C] fp16
        #pragma unroll
        for (int j = 0; j < 8; j++) {
            int d = j * 8 + 2 * (lane & 3);
            size_t o0 = ((size_t)b * SEQ + q0) * CH + h * DHD + d;
            size_t o1 = ((size_t)b * SEQ + q1) * CH + h * DHD + d;
            *(__half2*)&g_o[o0] = __floats2half2_rn(oc[j][0], oc[j][1]);
            *(__half2*)&g_o[o1] = __floats2half2_rn(oc[j][2], oc[j][3]);
        }

        __syncthreads();   // all reads of `buf` done before it is refilled next iteration
        buf ^= 1;
    }
}

// ---------------- launch ----------------
extern "C" void kernel_launch(void* const* d_in, const int* in_sizes, int n_in,
                              void* d_out, int out_size)
{
    (void)in_sizes; (void)n_in; (void)out_size;
    const float* x    = (const float*)d_in[0];
    const float* wqkv = (const float*)d_in[1];
    const float* wout = (const float*)d_in[2];
    const float* bvec = (const float*)d_in[3];
    const float* rel  = (const float*)d_in[4];
    float* out = (float*)d_out;

    cudaFuncSetAttribute(gemm_hmma<0>, cudaFuncAttributeMaxDynamicSharedMemorySize, SMEM_DYN);
    cudaFuncSetAttribute(gemm_hmma<1>, cudaFuncAttributeMaxDynamicSharedMemorySize, SMEM_DYN);
    cudaFuncSetAttribute(attn_kernel, cudaFuncAttributeMaxDynamicSharedMemorySize, ATT_SMEM);

    conv_x<<<8192, 256>>>(x);
    conv_w_bias<<<2048, 256>>>(wqkv, wout, rel);

    gemm_hmma<0><<<dim3(NQKV / BN, MROWS / BM), GT, SMEM_DYN>>>(nullptr, nullptr);
    attn_kernel<<<ATT_G, 128, ATT_SMEM>>>();
    gemm_hmma<1><<<dim3(CH / BN, MROWS / BM), GT, SMEM_DYN>>>(bvec, out);
}

// round 14
// speedup vs baseline: 1.0182x; 1.0182x over previous
#include <cuda_runtime.h>
#include <cuda_fp16.h>
#include <cstdint>
#include <cstddef>

// ---------------- problem dims ----------------
#define BATCH 2048
#define SEQ   64
#define CH    1024
#define NH    16
#define DHD   64
#define MROWS (BATCH*SEQ)   // 131072
#define KD    1024
#define NQKV  3072
#define NBH   (BATCH*NH)    // 32768

// ---------------- GEMM tiling ----------------
#define BM   128
#define BN   128
#define BK   64
#define PIPE 3
#define NSTAGE (KD/BK)          // 16
#define GT   128                // 4 warps, warp tile 64x64
#define ASTR (BK + 8)           // 72
#define BSTR (BN + 8)           // 136
#define A_BYTES (BM * ASTR * 2) // 18432
#define B_BYTES (BK * BSTR * 2) // 17408
#define STAGE_BYTES (A_BYTES + B_BYTES) // 35840
#define SMEM_DYN (PIPE * STAGE_BYTES)   // 107520

// ---------------- attention tiling ----------------
#define QKV_STR 72                       // padded row stride (halfs)
#define TILE_H  (SEQ * QKV_STR)          // 4608 halfs per tile
#define BUF_H   (3 * TILE_H)             // 13824 halfs per buffer
#define ATT_SMEM (2 * BUF_H * 2)         // 55296 bytes
#define ATT_G   592                      // persistent grid (4 per SM x 148)

// ---------------- scratch ----------------
__device__ __align__(256) __half g_x16[(size_t)MROWS * KD];
__device__ __align__(256) __half g_q[(size_t)BATCH * NH * SEQ * DHD];   // [B,H,L,dh]
__device__ __align__(256) __half g_k[(size_t)BATCH * NH * SEQ * DHD];
__device__ __align__(256) __half g_v[(size_t)BATCH * NH * SEQ * DHD];
__device__ __align__(256) __half g_o[(size_t)MROWS * CH];               // [B*L, C]
__device__ __align__(256) __half g_wqkv16[(size_t)KD * NQKV];           // [K,N] row-major
__device__ __align__(256) __half g_wout16[(size_t)KD * CH];             // [K,N] row-major
__device__ __align__(256) float  g_bias[NH * SEQ * SEQ];                // [H,64,64]

// ---------------- helpers ----------------
__device__ __forceinline__ uint32_t smem_u32(const void* p) {
    return (uint32_t)__cvta_generic_to_shared(p);
}
__device__ __forceinline__ void cp16(uint32_t s, const void* g) {
    asm volatile("cp.async.cg.shared.global [%0], [%1], 16;" :: "r"(s), "l"(g) : "memory");
}
__device__ __forceinline__ void ldsm_x4(uint32_t& r0, uint32_t& r1, uint32_t& r2, uint32_t& r3, uint32_t a) {
    asm volatile("ldmatrix.sync.aligned.m8n8.x4.shared.b16 {%0,%1,%2,%3}, [%4];"
                 : "=r"(r0), "=r"(r1), "=r"(r2), "=r"(r3) : "r"(a));
}
__device__ __forceinline__ void ldsm_x4t(uint32_t& r0, uint32_t& r1, uint32_t& r2, uint32_t& r3, uint32_t a) {
    asm volatile("ldmatrix.sync.aligned.m8n8.x4.trans.shared.b16 {%0,%1,%2,%3}, [%4];"
                 : "=r"(r0), "=r"(r1), "=r"(r2), "=r"(r3) : "r"(a));
}
__device__ __forceinline__ void mma_16816(float* c, const uint32_t* a, const uint32_t* b) {
    asm volatile("mma.sync.aligned.m16n8k16.row.col.f32.f16.f16.f32 "
                 "{%0,%1,%2,%3}, {%4,%5,%6,%7}, {%8,%9}, {%0,%1,%2,%3};"
                 : "+f"(c[0]), "+f"(c[1]), "+f"(c[2]), "+f"(c[3])
                 : "r"(a[0]), "r"(a[1]), "r"(a[2]), "r"(a[3]), "r"(b[0]), "r"(b[1]));
}
__device__ __forceinline__ uint32_t h2_as_u32(__half2 h) {
    return *reinterpret_cast<uint32_t*>(&h);
}

// ---------------- prep kernels (f32 -> f16, vectorized) ----------------
__global__ void conv_x(const float* __restrict__ x) {
    size_t step = (size_t)gridDim.x * blockDim.x * 4;
    size_t total = (size_t)MROWS * KD;
    for (size_t i = ((size_t)blockIdx.x * blockDim.x + threadIdx.x) * 4; i < total; i += step) {
        float4 v = *(const float4*)(x + i);
        uint2 u = make_uint2(h2_as_u32(__floats2half2_rn(v.x, v.y)),
                             h2_as_u32(__floats2half2_rn(v.z, v.w)));
        *(uint2*)(g_x16 + i) = u;
    }
}
// fused: weights f32->f16 + bias table build
__global__ void conv_w_bias(const float* __restrict__ wqkv, const float* __restrict__ wout,
                            const float* __restrict__ rel) {
    size_t t1 = (size_t)KD * NQKV;
    size_t total = t1 + (size_t)KD * CH;
    size_t step = (size_t)gridDim.x * blockDim.x * 4;
    for (size_t i = ((size_t)blockIdx.x * blockDim.x + threadIdx.x) * 4; i < total; i += step) {
        const float* src = (i < t1) ? (wqkv + i) : (wout + (i - t1));
        __half* dst = (i < t1) ? (g_wqkv16 + i) : (g_wout16 + (i - t1));
        float4 v = *(const float4*)src;
        uint2 u = make_uint2(h2_as_u32(__floats2half2_rn(v.x, v.y)),
                             h2_as_u32(__floats2half2_rn(v.z, v.w)));
        *(uint2*)dst = u;
    }
    int gi = blockIdx.x * blockDim.x + threadIdx.x;
    if (gi < NH * SEQ * SEQ) {
        int h = gi >> 12, q = (gi >> 6) & 63, k = gi & 63;
        int dr = (q >> 3) - (k >> 3) + 7;
        int dc = (q & 7) - (k & 7) + 7;
        g_bias[gi] = rel[(dr * 15 + dc) * NH + h];
    }
}

// ---------------- fp16 HMMA GEMM: 4 warps, warp tile 64x64, cp.async 3-stage ----------------
template<int EPI>
__global__ __launch_bounds__(GT, 2)
void gemm_hmma(const float* __restrict__ bvec, float* __restrict__ outF)
{
    extern __shared__ __align__(16) char dynsm[];
    constexpr int ND = (EPI == 0) ? NQKV : CH;
    const __half* __restrict__ A  = (EPI == 0) ? g_x16 : g_o;
    const __half* __restrict__ Bw = (EPI == 0) ? g_wqkv16 : g_wout16;

    const int tid = threadIdx.x;
    const int w = tid >> 5, lane = tid & 31;
    const int wm = w >> 1, wn = w & 1;     // 2x2 warps, warp tile 64x64
    const int m0 = blockIdx.y * BM;
    const int n0 = blockIdx.x * BN;

    float acc[4][8][4];
    #pragma unroll
    for (int mi = 0; mi < 4; mi++)
        #pragma unroll
        for (int j = 0; j < 8; j++)
            #pragma unroll
            for (int q = 0; q < 4; q++) acc[mi][j][q] = 0.f;

    const uint32_t sb = smem_u32(dynsm);

    const int arow = tid >> 3, ac = tid & 7;
    const int brow = tid >> 4, bc = tid & 15;

    auto load_stage = [&](int s) {
        uint32_t base = sb + (uint32_t)(s % PIPE) * STAGE_BYTES;
        const __half* ag = A + (size_t)m0 * KD + s * BK;
        const __half* bg = Bw + (size_t)(s * BK) * ND + n0;
        #pragma unroll
        for (int i = 0; i < 8; i++) {
            int r = arow + i * 16;
            cp16(base + (uint32_t)(r * ASTR + ac * 8) * 2, ag + (size_t)r * KD + ac * 8);
        }
        #pragma unroll
        for (int i = 0; i < 8; i++) {
            int r = brow + i * 8;
            cp16(base + A_BYTES + (uint32_t)(r * BSTR + bc * 8) * 2, bg + (size_t)r * ND + bc * 8);
        }
        asm volatile("cp.async.commit_group;" ::: "memory");
    };

    load_stage(0);
    load_stage(1);

    const int a_row_sel = wm * 64 + (lane & 15);
    const int a_col_sel = (lane >> 4) * 8;
    const int b_mi2 = lane >> 3, b_r = lane & 7;
    const int b_row_sel = (b_mi2 & 1) * 8 + b_r;
    const int b_col_sel = wn * 64 + (b_mi2 >> 1) * 8;

    uint32_t afr[2][4][4];
    uint32_t bfr[2][8][2];

    auto load_frags = [&](int buf, uint32_t aBase, uint32_t bBase, int kk) {
        #pragma unroll
        for (int mi = 0; mi < 4; mi++) {
            uint32_t ad = aBase + (uint32_t)((a_row_sel + mi * 16) * ASTR + kk * 16 + a_col_sel) * 2;
            ldsm_x4(afr[buf][mi][0], afr[buf][mi][1], afr[buf][mi][2], afr[buf][mi][3], ad);
        }
        #pragma unroll
        for (int j2 = 0; j2 < 4; j2++) {
            uint32_t bd = bBase + (uint32_t)((kk * 16 + b_row_sel) * BSTR + b_col_sel + j2 * 16) * 2;
            uint32_t r0, r1, r2, r3;
            ldsm_x4t(r0, r1, r2, r3, bd);
            bfr[buf][2 * j2][0] = r0;     bfr[buf][2 * j2][1] = r1;
            bfr[buf][2 * j2 + 1][0] = r2; bfr[buf][2 * j2 + 1][1] = r3;
        }
    };

    for (int kt = 0; kt < NSTAGE; kt++) {
        if (kt + 1 < NSTAGE) asm volatile("cp.async.wait_group 1;" ::: "memory");
        else                 asm volatile("cp.async.wait_group 0;" ::: "memory");
        __syncthreads();
        if (kt + 2 < NSTAGE) load_stage(kt + 2);

        uint32_t aBase = sb + (uint32_t)(kt % PIPE) * STAGE_BYTES;
        uint32_t bBase = aBase + A_BYTES;

        load_frags(0, aBase, bBase, 0);
        #pragma unroll
        for (int kk = 0; kk < 4; kk++) {
            int cur = kk & 1;
            if (kk < 3) load_frags(cur ^ 1, aBase, bBase, kk + 1);
            #pragma unroll
            for (int mi = 0; mi < 4; mi++)
                #pragma unroll
                for (int j = 0; j < 8; j++)
                    mma_16816(acc[mi][j], afr[cur][mi], bfr[cur][j]);
        }
    }

    // ---------------- epilogue ----------------
    const int rbase = m0 + wm * 64;
    const int cbase = n0 + wn * 64;
    if constexpr (EPI == 0) {
        int part = cbase >> 10;
        int h = (cbase >> 6) & (NH - 1);
        __half* dst = (part == 0) ? g_q : (part == 1) ? g_k : g_v;
        #pragma unroll
        for (int mi = 0; mi < 4; mi++) {
            int row0 = rbase + mi * 16 + (lane >> 2);
            int row1 = row0 + 8;
            size_t base0 = ((size_t)((row0 >> 6) * NH + h)) * 4096 + (size_t)(row0 & 63) * 64;
            size_t base1 = ((size_t)((row1 >> 6) * NH + h)) * 4096 + (size_t)(row1 & 63) * 64;
            #pragma unroll
            for (int j = 0; j < 8; j++) {
                int d = j * 8 + 2 * (lane & 3);
                *(__half2*)&dst[base0 + d] = __floats2half2_rn(acc[mi][j][0], acc[mi][j][1]);
                *(__half2*)&dst[base1 + d] = __floats2half2_rn(acc[mi][j][2], acc[mi][j][3]);
            }
        }
    } else {
        #pragma unroll
        for (int mi = 0; mi < 4; mi++) {
            int row0 = rbase + mi * 16 + (lane >> 2);
            int row1 = row0 + 8;
            #pragma unroll
            for (int j = 0; j < 8; j++) {
                int col = cbase + j * 8 + 2 * (lane & 3);
                float2 bb = *(const float2*)&bvec[col];
                float2 v0 = make_float2(acc[mi][j][0] + bb.x, acc[mi][j][1] + bb.y);
                float2 v1 = make_float2(acc[mi][j][2] + bb.x, acc[mi][j][3] + bb.y);
                *(float2*)&outF[(size_t)row0 * CH + col] = v0;
                *(float2*)&outF[(size_t)row1 * CH + col] = v1;
            }
        }
    }
}

// ---------------- persistent attention: double-buffered cp.async over (b,h) ----------------
// per buffer (halfs): Q at +0, K at +TILE_H, V at +2*TILE_H; row stride QKV_STR
__global__ __launch_bounds__(128, 4)
void attn_kernel()
{
    extern __shared__ __align__(16) __half attsm[];
    const int tid = threadIdx.x;
    const int w = tid >> 5, lane = tid & 31;
    const uint32_t sb = smem_u32(attsm);

    auto load_bh = [&](int buf, int bh) {
        uint32_t base = sb + (uint32_t)buf * BUF_H * 2;
        size_t tb = (size_t)bh * (SEQ * DHD);
        #pragma unroll
        for (int t = 0; t < 3; t++) {
            const __half* src = (t == 0) ? g_q : (t == 1) ? g_k : g_v;
            uint32_t tbase = base + (uint32_t)t * TILE_H * 2;
            #pragma unroll
            for (int i = 0; i < 4; i++) {
                int u = tid + i * 128;
                int row = u >> 3, c8 = (u & 7) * 8;
                cp16(tbase + (uint32_t)(row * QKV_STR + c8) * 2, src + tb + row * DHD + c8);
            }
        }
        asm volatile("cp.async.commit_group;" ::: "memory");
    };

    const int m0 = w * 16;
    const int q0 = m0 + (lane >> 2);
    const int q1 = q0 + 8;

    int i0 = blockIdx.x;
    if (i0 < NBH) load_bh(0, i0);

    int buf = 0;
    for (int i = i0; i < NBH; i += ATT_G) {
        int inext = i + ATT_G;
        // issue next prefetch first
        if (inext < NBH) load_bh(buf ^ 1, inext);

        const int b = i >> 4;
        const int h = i & (NH - 1);
        const float* bg = g_bias + h * (SEQ * SEQ);

        // issue bias loads BEFORE waiting on cp.async: their L2 latency overlaps the wait
        float sc[8][4];
        #pragma unroll
        for (int j = 0; j < 8; j++) {
            int col = j * 8 + 2 * (lane & 3);
            float2 t0 = __ldg((const float2*)(bg + q0 * SEQ + col));
            float2 t1 = __ldg((const float2*)(bg + q1 * SEQ + col));
            sc[j][0] = t0.x * 8.f; sc[j][1] = t0.y * 8.f;
            sc[j][2] = t1.x * 8.f; sc[j][3] = t1.y * 8.f;
        }

        if (inext < NBH) asm volatile("cp.async.wait_group 1;" ::: "memory");
        else             asm volatile("cp.async.wait_group 0;" ::: "memory");
        __syncthreads();   // buffer `buf` data visible to all warps

        const uint32_t bQ = sb + (uint32_t)buf * BUF_H * 2;
        const uint32_t bK = bQ + TILE_H * 2;
        const uint32_t bV = bK + TILE_H * 2;

        // S = Q @ K^T (+ 8*bias preloaded)
        #pragma unroll
        for (int kk = 0; kk < 4; kk++) {
            uint32_t a[4];
            uint32_t ad = bQ + (uint32_t)((m0 + (lane & 15)) * QKV_STR + kk * 16 + (lane >> 4) * 8) * 2;
            ldsm_x4(a[0], a[1], a[2], a[3], ad);
            uint32_t kf[8][2];
            #pragma unroll
            for (int j2 = 0; j2 < 4; j2++) {
                int mi = lane >> 3, r = lane & 7;
                uint32_t kad = bK + (uint32_t)((j2 * 16 + (mi >> 1) * 8 + r) * QKV_STR + kk * 16 + (mi & 1) * 8) * 2;
                uint32_t r0, r1, r2, r3;
                ldsm_x4(r0, r1, r2, r3, kad);
                kf[2 * j2][0] = r0;     kf[2 * j2][1] = r1;
                kf[2 * j2 + 1][0] = r2; kf[2 * j2 + 1][1] = r3;
            }
            #pragma unroll
            for (int j = 0; j < 8; j++) mma_16816(sc[j], a, kf[j]);
        }

        // softmax (scale by 0.125 exactly)
        float mx0 = -1e30f, mx1 = -1e30f;
        #pragma unroll
        for (int j = 0; j < 8; j++) {
            sc[j][0] *= 0.125f; sc[j][1] *= 0.125f;
            sc[j][2] *= 0.125f; sc[j][3] *= 0.125f;
            mx0 = fmaxf(mx0, fmaxf(sc[j][0], sc[j][1]));
            mx1 = fmaxf(mx1, fmaxf(sc[j][2], sc[j][3]));
        }
        mx0 = fmaxf(mx0, __shfl_xor_sync(0xffffffffu, mx0, 1));
        mx0 = fmaxf(mx0, __shfl_xor_sync(0xffffffffu, mx0, 2));
        mx1 = fmaxf(mx1, __shfl_xor_sync(0xffffffffu, mx1, 1));
        mx1 = fmaxf(mx1, __shfl_xor_sync(0xffffffffu, mx1, 2));
        float s0 = 0.f, s1 = 0.f;
        #pragma unroll
        for (int j = 0; j < 8; j++) {
            sc[j][0] = __expf(sc[j][0] - mx0);
            sc[j][1] = __expf(sc[j][1] - mx0);
            sc[j][2] = __expf(sc[j][2] - mx1);
            sc[j][3] = __expf(sc[j][3] - mx1);
            s0 += sc[j][0] + sc[j][1];
            s1 += sc[j][2] + sc[j][3];
        }
        s0 += __shfl_xor_sync(0xffffffffu, s0, 1);
        s0 += __shfl_xor_sync(0xffffffffu, s0, 2);
        s1 += __shfl_xor_sync(0xffffffffu, s1, 1);
        s1 += __shfl_xor_sync(0xffffffffu, s1, 2);
        float inv0 = 1.f / s0;
        float inv1 = 1.f / s1;

        uint32_t pf[8][2];
        #pragma unroll
        for (int j = 0; j < 8; j++) {
            pf[j][0] = h2_as_u32(__floats2half2_rn(sc[j][0] * inv0, sc[j][1] * inv0));
            pf[j][1] = h2_as_u32(__floats2half2_rn(sc[j][2] * inv1, sc[j][3] * inv1));
        }

        // O = P @ V
        float oc[8][4];
        #pragma unroll
        for (int j = 0; j < 8; j++)
            #pragma unroll
            for (int q = 0; q < 4; q++) oc[j][q] = 0.f;

        #pragma unroll
        for (int kk2 = 0; kk2 < 4; kk2++) {
            uint32_t a2[4] = { pf[2 * kk2][0], pf[2 * kk2][1], pf[2 * kk2 + 1][0], pf[2 * kk2 + 1][1] };
            uint32_t vf[8][2];
            #pragma unroll
            for (int dj2 = 0; dj2 < 4; dj2++) {
                int mi = lane >> 3, r = lane & 7;
                uint32_t vad = bV + (uint32_t)((kk2 * 16 + (mi & 1) * 8 + r) * QKV_STR + dj2 * 16 + (mi >> 1) * 8) * 2;
                uint32_t r0, r1, r2, r3;
                ldsm_x4t(r0, r1, r2, r3, vad);
                vf[2 * dj2][0] = r0;     vf[2 * dj2][1] = r1;
                vf[2 * dj2 + 1][0] = r2; vf[2 * dj2 + 1][1] = r3;
            }
            #pragma unroll
            for (int j = 0; j < 8; j++) mma_16816(oc[j], a2, vf[j]);
        }

        // ---- stage O into the (now dead) Q region of the CURRENT buffer (warp-local rows) ----
        #pragma unroll
        for (int j = 0; j < 8; j++) {
            int d = j * 8 + 2 * (lane & 3);
            uint32_t a0 = bQ + (uint32_t)(q0 * QKV_STR + d) * 2;
            uint32_t a1 = bQ + (uint32_t)(q1 * QKV_STR + d) * 2;
            uint32_t h0 = h2_as_u32(__floats2half2_rn(oc[j][0], oc[j][1]));
            uint32_t h1 = h2_as_u32(__floats2half2_rn(oc[j][2], oc[j][3]));
            asm volatile("st.shared.b32 [%0], %1;" :: "r"(a0), "r"(h0) : "memory");
            asm volatile("st.shared.b32 [%0], %1;" :: "r"(a1), "r"(h1) : "memory");
        }
        __syncwarp();
        // coalesced write-out: 4 x STG.128, each instr covers 4 full 128B rows
        #pragma unroll
        for (int ii = 0; ii < 4; ii++) {
            int c = ii * 32 + lane;          // 0..127 chunk id within warp tile
            int r = c >> 3;                  // local row 0..15
            int c16 = c & 7;                 // 16B chunk within row
            uint32_t sa = bQ + (uint32_t)((m0 + r) * QKV_STR) * 2 + c16 * 16;
            uint4 val;
            asm volatile("ld.shared.v4.b32 {%0,%1,%2,%3}, [%4];"
                         : "=r"(val.x), "=r"(val.y), "=r"(val.z), "=r"(val.w) : "r"(sa));
            size_t go = ((size_t)b * SEQ + m0 + r) * CH + h * DHD + c16 * 8;
            *(uint4*)(g_o + go) = val;
        }

        __syncthreads();   // all reads of `buf` done before it is refilled next iteration
        buf ^= 1;
    }
}

// ---------------- launch ----------------
extern "C" void kernel_launch(void* const* d_in, const int* in_sizes, int n_in,
                              void* d_out, int out_size)
{
    (void)in_sizes; (void)n_in; (void)out_size;
    const float* x    = (const float*)d_in[0];
    const float* wqkv = (const float*)d_in[1];
    const float* wout = (const float*)d_in[2];
    const float* bvec = (const float*)d_in[3];
    const float* rel  = (const float*)d_in[4];
    float* out = (float*)d_out;

    cudaFuncSetAttribute(gemm_hmma<0>, cudaFuncAttributeMaxDynamicSharedMemorySize, SMEM_DYN);
    cudaFuncSetAttribute(gemm_hmma<1>, cudaFuncAttributeMaxDynamicSharedMemorySize, SMEM_DYN);
    cudaFuncSetAttribute(attn_kernel, cudaFuncAttributeMaxDynamicSharedMemorySize, ATT_SMEM);

    conv_x<<<8192, 256>>>(x);
    conv_w_bias<<<2048, 256>>>(wqkv, wout, rel);

    gemm_hmma<0><<<dim3(NQKV / BN, MROWS / BM), GT, SMEM_DYN>>>(nullptr, nullptr);
    attn_kernel<<<ATT_G, 128, ATT_SMEM>>>();
    gemm_hmma<1><<<dim3(CH / BN, MROWS / BM), GT, SMEM_DYN>>>(bvec, out);
}

// round 15
// speedup vs baseline: 1.0381x; 1.0196x over previous
#include <cuda_runtime.h>
#include <cuda_fp16.h>
#include <cstdint>
#include <cstddef>

// ---------------- problem dims ----------------
#define BATCH 2048
#define SEQ   64
#define CH    1024
#define NH    16
#define DHD   64
#define MROWS (BATCH*SEQ)   // 131072
#define KD    1024
#define NQKV  3072
#define NBH   (BATCH*NH)    // 32768

// ---------------- GEMM tiling ----------------
#define BM   128
#define BN   128
#define BK   64
#define PIPE 3
#define NSTAGE (KD/BK)          // 16
#define GT   128                // 4 warps, warp tile 64x64
#define ASTR (BK + 8)           // 72
#define BSTR (BN + 8)           // 136
#define A_BYTES (BM * ASTR * 2) // 18432
#define B_BYTES (BK * BSTR * 2) // 17408
#define STAGE_BYTES (A_BYTES + B_BYTES) // 35840
#define SMEM_DYN (PIPE * STAGE_BYTES)   // 107520
#define OSTR (DHD + 8)          // 72, epilogue staging stride
#define OWARP_BYTES (64 * OSTR * 2)     // 9216 per warp

// ---------------- attention tiling ----------------
#define QKV_STR 72                       // padded row stride (halfs)
#define TILE_H  (SEQ * QKV_STR)          // 4608 halfs per tile
#define BUF_H   (3 * TILE_H)             // 13824 halfs per buffer
#define ATT_SMEM (2 * BUF_H * 2)         // 55296 bytes
#define ATT_G   592                      // persistent grid (4 per SM x 148)

// ---------------- scratch ----------------
__device__ __align__(256) __half g_x16[(size_t)MROWS * KD];
__device__ __align__(256) __half g_q[(size_t)BATCH * NH * SEQ * DHD];   // [B,H,L,dh] (pre-scaled by 0.125)
__device__ __align__(256) __half g_k[(size_t)BATCH * NH * SEQ * DHD];
__device__ __align__(256) __half g_v[(size_t)BATCH * NH * SEQ * DHD];
__device__ __align__(256) __half g_o[(size_t)MROWS * CH];               // [B*L, C]
__device__ __align__(256) __half g_wqkv16[(size_t)KD * NQKV];           // [K,N] row-major
__device__ __align__(256) __half g_wout16[(size_t)KD * CH];             // [K,N] row-major
__device__ __align__(256) float  g_bias[NH * SEQ * SEQ];                // [H,64,64]

// ---------------- helpers ----------------
__device__ __forceinline__ uint32_t smem_u32(const void* p) {
    return (uint32_t)__cvta_generic_to_shared(p);
}
__device__ __forceinline__ void cp16(uint32_t s, const void* g) {
    asm volatile("cp.async.cg.shared.global [%0], [%1], 16;" :: "r"(s), "l"(g) : "memory");
}
__device__ __forceinline__ void ldsm_x4(uint32_t& r0, uint32_t& r1, uint32_t& r2, uint32_t& r3, uint32_t a) {
    asm volatile("ldmatrix.sync.aligned.m8n8.x4.shared.b16 {%0,%1,%2,%3}, [%4];"
                 : "=r"(r0), "=r"(r1), "=r"(r2), "=r"(r3) : "r"(a));
}
__device__ __forceinline__ void ldsm_x4t(uint32_t& r0, uint32_t& r1, uint32_t& r2, uint32_t& r3, uint32_t a) {
    asm volatile("ldmatrix.sync.aligned.m8n8.x4.trans.shared.b16 {%0,%1,%2,%3}, [%4];"
                 : "=r"(r0), "=r"(r1), "=r"(r2), "=r"(r3) : "r"(a));
}
__device__ __forceinline__ void mma_16816(float* c, const uint32_t* a, const uint32_t* b) {
    asm volatile("mma.sync.aligned.m16n8k16.row.col.f32.f16.f16.f32 "
                 "{%0,%1,%2,%3}, {%4,%5,%6,%7}, {%8,%9}, {%0,%1,%2,%3};"
                 : "+f"(c[0]), "+f"(c[1]), "+f"(c[2]), "+f"(c[3])
                 : "r"(a[0]), "r"(a[1]), "r"(a[2]), "r"(a[3]), "r"(b[0]), "r"(b[1]));
}
__device__ __forceinline__ uint32_t h2_as_u32(__half2 h) {
    return *reinterpret_cast<uint32_t*>(&h);
}

// ---------------- fused prep: x f32->f16, weights f32->f16, bias table ----------------
__global__ void conv_all(const float* __restrict__ x,
                         const float* __restrict__ wqkv, const float* __restrict__ wout,
                         const float* __restrict__ rel) {
    size_t tx = (size_t)MROWS * KD;
    size_t t1 = (size_t)KD * NQKV;
    size_t total = tx + t1 + (size_t)KD * CH;
    size_t step = (size_t)gridDim.x * blockDim.x * 4;
    for (size_t i = ((size_t)blockIdx.x * blockDim.x + threadIdx.x) * 4; i < total; i += step) {
        const float* src;
        __half* dst;
        if (i < tx)            { src = x + i;              dst = g_x16 + i; }
        else if (i < tx + t1)  { src = wqkv + (i - tx);    dst = g_wqkv16 + (i - tx); }
        else                   { src = wout + (i - tx - t1); dst = g_wout16 + (i - tx - t1); }
        float4 v = *(const float4*)src;
        uint2 u = make_uint2(h2_as_u32(__floats2half2_rn(v.x, v.y)),
                             h2_as_u32(__floats2half2_rn(v.z, v.w)));
        *(uint2*)dst = u;
    }
    int gi = blockIdx.x * blockDim.x + threadIdx.x;
    if (gi < NH * SEQ * SEQ) {
        int h = gi >> 12, q = (gi >> 6) & 63, k = gi & 63;
        int dr = (q >> 3) - (k >> 3) + 7;
        int dc = (q & 7) - (k & 7) + 7;
        g_bias[gi] = rel[(dr * 15 + dc) * NH + h];
    }
}

// ---------------- fp16 HMMA GEMM: 4 warps, warp tile 64x64, cp.async 3-stage ----------------
// EPI 0: g_x16[M,K] @ g_wqkv16[K,3072] -> scatter q/k/v fp16 (q pre-scaled 0.125), coalesced via smem
// EPI 1: g_o  [M,K] @ g_wout16[K,1024] + bias -> out f32
template<int EPI>
__global__ __launch_bounds__(GT, 2)
void gemm_hmma(const float* __restrict__ bvec, float* __restrict__ outF)
{
    extern __shared__ __align__(16) char dynsm[];
    constexpr int ND = (EPI == 0) ? NQKV : CH;
    const __half* __restrict__ A  = (EPI == 0) ? g_x16 : g_o;
    const __half* __restrict__ Bw = (EPI == 0) ? g_wqkv16 : g_wout16;

    const int tid = threadIdx.x;
    const int w = tid >> 5, lane = tid & 31;
    const int wm = w >> 1, wn = w & 1;     // 2x2 warps, warp tile 64x64
    const int m0 = blockIdx.y * BM;
    const int n0 = blockIdx.x * BN;

    float acc[4][8][4];
    #pragma unroll
    for (int mi = 0; mi < 4; mi++)
        #pragma unroll
        for (int j = 0; j < 8; j++)
            #pragma unroll
            for (int q = 0; q < 4; q++) acc[mi][j][q] = 0.f;

    const uint32_t sb = smem_u32(dynsm);

    const int arow = tid >> 3, ac = tid & 7;
    const int brow = tid >> 4, bc = tid & 15;

    auto load_stage = [&](int s) {
        uint32_t base = sb + (uint32_t)(s % PIPE) * STAGE_BYTES;
        const __half* ag = A + (size_t)m0 * KD + s * BK;
        const __half* bg = Bw + (size_t)(s * BK) * ND + n0;
        #pragma unroll
        for (int i = 0; i < 8; i++) {
            int r = arow + i * 16;
            cp16(base + (uint32_t)(r * ASTR + ac * 8) * 2, ag + (size_t)r * KD + ac * 8);
        }
        #pragma unroll
        for (int i = 0; i < 8; i++) {
            int r = brow + i * 8;
            cp16(base + A_BYTES + (uint32_t)(r * BSTR + bc * 8) * 2, bg + (size_t)r * ND + bc * 8);
        }
        asm volatile("cp.async.commit_group;" ::: "memory");
    };

    load_stage(0);
    load_stage(1);

    const int a_row_sel = wm * 64 + (lane & 15);
    const int a_col_sel = (lane >> 4) * 8;
    const int b_mi2 = lane >> 3, b_r = lane & 7;
    const int b_row_sel = (b_mi2 & 1) * 8 + b_r;
    const int b_col_sel = wn * 64 + (b_mi2 >> 1) * 8;

    uint32_t afr[2][4][4];
    uint32_t bfr[2][8][2];

    auto load_frags = [&](int buf, uint32_t aBase, uint32_t bBase, int kk) {
        #pragma unroll
        for (int mi = 0; mi < 4; mi++) {
            uint32_t ad = aBase + (uint32_t)((a_row_sel + mi * 16) * ASTR + kk * 16 + a_col_sel) * 2;
            ldsm_x4(afr[buf][mi][0], afr[buf][mi][1], afr[buf][mi][2], afr[buf][mi][3], ad);
        }
        #pragma unroll
        for (int j2 = 0; j2 < 4; j2++) {
            uint32_t bd = bBase + (uint32_t)((kk * 16 + b_row_sel) * BSTR + b_col_sel + j2 * 16) * 2;
            uint32_t r0, r1, r2, r3;
            ldsm_x4t(r0, r1, r2, r3, bd);
            bfr[buf][2 * j2][0] = r0;     bfr[buf][2 * j2][1] = r1;
            bfr[buf][2 * j2 + 1][0] = r2; bfr[buf][2 * j2 + 1][1] = r3;
        }
    };

    for (int kt = 0; kt < NSTAGE; kt++) {
        if (kt + 1 < NSTAGE) asm volatile("cp.async.wait_group 1;" ::: "memory");
        else                 asm volatile("cp.async.wait_group 0;" ::: "memory");
        __syncthreads();
        if (kt + 2 < NSTAGE) load_stage(kt + 2);

        uint32_t aBase = sb + (uint32_t)(kt % PIPE) * STAGE_BYTES;
        uint32_t bBase = aBase + A_BYTES;

        load_frags(0, aBase, bBase, 0);
        #pragma unroll
        for (int kk = 0; kk < 4; kk++) {
            int cur = kk & 1;
            if (kk < 3) load_frags(cur ^ 1, aBase, bBase, kk + 1);
            #pragma unroll
            for (int mi = 0; mi < 4; mi++)
                #pragma unroll
                for (int j = 0; j < 8; j++)
                    mma_16816(acc[mi][j], afr[cur][mi], bfr[cur][j]);
        }
    }

    // ---------------- epilogue ----------------
    const int rbase = m0 + wm * 64;
    const int cbase = n0 + wn * 64;
    if constexpr (EPI == 0) {
        // Each warp's 64x64 tile -> one contiguous 8KB block of q/k/v.
        // Stage in (now-dead) pipeline smem, then fully coalesced STG.128.
        __syncthreads();   // all warps done reading stage buffers
        int part = cbase >> 10;
        int h = (cbase >> 6) & (NH - 1);
        __half* dst = (part == 0) ? g_q : (part == 1) ? g_k : g_v;
        const float qs = (part == 0) ? 0.125f : 1.0f;   // exact power-of-2 pre-scale for Q
        const uint32_t wbase = sb + (uint32_t)w * OWARP_BYTES;
        #pragma unroll
        for (int mi = 0; mi < 4; mi++) {
            int r0 = mi * 16 + (lane >> 2);
            int r1 = r0 + 8;
            #pragma unroll
            for (int j = 0; j < 8; j++) {
                int c = j * 8 + 2 * (lane & 3);
                uint32_t h0 = h2_as_u32(__floats2half2_rn(acc[mi][j][0] * qs, acc[mi][j][1] * qs));
                uint32_t h1 = h2_as_u32(__floats2half2_rn(acc[mi][j][2] * qs, acc[mi][j][3] * qs));
                asm volatile("st.shared.b32 [%0], %1;" :: "r"(wbase + (uint32_t)(r0 * OSTR + c) * 2), "r"(h0) : "memory");
                asm volatile("st.shared.b32 [%0], %1;" :: "r"(wbase + (uint32_t)(r1 * OSTR + c) * 2), "r"(h1) : "memory");
            }
        }
        __syncwarp();
        size_t dbase = ((size_t)((rbase >> 6) * NH + h)) * 4096;   // contiguous 4096-half block
        #pragma unroll
        for (int it = 0; it < 16; it++) {
            int row = it * 4 + (lane >> 3);
            int chunk = lane & 7;
            uint32_t sa = wbase + (uint32_t)(row * OSTR) * 2 + chunk * 16;
            uint4 val;
            asm volatile("ld.shared.v4.b32 {%0,%1,%2,%3}, [%4];"
                         : "=r"(val.x), "=r"(val.y), "=r"(val.z), "=r"(val.w) : "r"(sa));
            *(uint4*)(dst + dbase + row * DHD + chunk * 8) = val;
        }
    } else {
        #pragma unroll
        for (int mi = 0; mi < 4; mi++) {
            int row0 = rbase + mi * 16 + (lane >> 2);
            int row1 = row0 + 8;
            #pragma unroll
            for (int j = 0; j < 8; j++) {
                int col = cbase + j * 8 + 2 * (lane & 3);
                float2 bb = *(const float2*)&bvec[col];
                float2 v0 = make_float2(acc[mi][j][0] + bb.x, acc[mi][j][1] + bb.y);
                float2 v1 = make_float2(acc[mi][j][2] + bb.x, acc[mi][j][3] + bb.y);
                *(float2*)&outF[(size_t)row0 * CH + col] = v0;
                *(float2*)&outF[(size_t)row1 * CH + col] = v1;
            }
        }
    }
}

// ---------------- persistent attention: double-buffered cp.async over (b,h) ----------------
// per buffer (halfs): Q at +0, K at +TILE_H, V at +2*TILE_H; row stride QKV_STR
// Q is pre-scaled by 0.125 -> S = Q'K^T + bias directly, no post-scale.
__global__ __launch_bounds__(128, 4)
void attn_kernel()
{
    extern __shared__ __align__(16) __half attsm[];
    const int tid = threadIdx.x;
    const int w = tid >> 5, lane = tid & 31;
    const uint32_t sb = smem_u32(attsm);

    auto load_bh = [&](int buf, int bh) {
        uint32_t base = sb + (uint32_t)buf * BUF_H * 2;
        size_t tb = (size_t)bh * (SEQ * DHD);
        #pragma unroll
        for (int t = 0; t < 3; t++) {
            const __half* src = (t == 0) ? g_q : (t == 1) ? g_k : g_v;
            uint32_t tbase = base + (uint32_t)t * TILE_H * 2;
            #pragma unroll
            for (int i = 0; i < 4; i++) {
                int u = tid + i * 128;
                int row = u >> 3, c8 = (u & 7) * 8;
                cp16(tbase + (uint32_t)(row * QKV_STR + c8) * 2, src + tb + row * DHD + c8);
            }
        }
        asm volatile("cp.async.commit_group;" ::: "memory");
    };

    const int m0 = w * 16;
    const int q0 = m0 + (lane >> 2);
    const int q1 = q0 + 8;

    int i0 = blockIdx.x;
    if (i0 < NBH) load_bh(0, i0);

    int buf = 0;
    for (int i = i0; i < NBH; i += ATT_G) {
        int inext = i + ATT_G;
        // issue next prefetch first
        if (inext < NBH) load_bh(buf ^ 1, inext);

        const int b = i >> 4;
        const int h = i & (NH - 1);
        const float* bg = g_bias + h * (SEQ * SEQ);

        // issue bias loads BEFORE waiting on cp.async: their L2 latency overlaps the wait
        float sc[8][4];
        #pragma unroll
        for (int j = 0; j < 8; j++) {
            int col = j * 8 + 2 * (lane & 3);
            float2 t0 = __ldg((const float2*)(bg + q0 * SEQ + col));
            float2 t1 = __ldg((const float2*)(bg + q1 * SEQ + col));
            sc[j][0] = t0.x; sc[j][1] = t0.y;
            sc[j][2] = t1.x; sc[j][3] = t1.y;
        }

        if (inext < NBH) asm volatile("cp.async.wait_group 1;" ::: "memory");
        else             asm volatile("cp.async.wait_group 0;" ::: "memory");
        __syncthreads();   // buffer `buf` data visible to all warps

        const uint32_t bQ = sb + (uint32_t)buf * BUF_H * 2;
        const uint32_t bK = bQ + TILE_H * 2;
        const uint32_t bV = bK + TILE_H * 2;

        // S = Q' @ K^T + bias (Q' pre-scaled by 0.125)
        #pragma unroll
        for (int kk = 0; kk < 4; kk++) {
            uint32_t a[4];
            uint32_t ad = bQ + (uint32_t)((m0 + (lane & 15)) * QKV_STR + kk * 16 + (lane >> 4) * 8) * 2;
            ldsm_x4(a[0], a[1], a[2], a[3], ad);
            uint32_t kf[8][2];
            #pragma unroll
            for (int j2 = 0; j2 < 4; j2++) {
                int mi = lane >> 3, r = lane & 7;
                uint32_t kad = bK + (uint32_t)((j2 * 16 + (mi >> 1) * 8 + r) * QKV_STR + kk * 16 + (mi & 1) * 8) * 2;
                uint32_t r0, r1, r2, r3;
                ldsm_x4(r0, r1, r2, r3, kad);
                kf[2 * j2][0] = r0;     kf[2 * j2][1] = r1;
                kf[2 * j2 + 1][0] = r2; kf[2 * j2 + 1][1] = r3;
            }
            #pragma unroll
            for (int j = 0; j < 8; j++) mma_16816(sc[j], a, kf[j]);
        }

        // softmax
        float mx0 = -1e30f, mx1 = -1e30f;
        #pragma unroll
        for (int j = 0; j < 8; j++) {
            mx0 = fmaxf(mx0, fmaxf(sc[j][0], sc[j][1]));
            mx1 = fmaxf(mx1, fmaxf(sc[j][2], sc[j][3]));
        }
        mx0 = fmaxf(mx0, __shfl_xor_sync(0xffffffffu, mx0, 1));
        mx0 = fmaxf(mx0, __shfl_xor_sync(0xffffffffu, mx0, 2));
        mx1 = fmaxf(mx1, __shfl_xor_sync(0xffffffffu, mx1, 1));
        mx1 = fmaxf(mx1, __shfl_xor_sync(0xffffffffu, mx1, 2));
        float s0 = 0.f, s1 = 0.f;
        #pragma unroll
        for (int j = 0; j < 8; j++) {
            sc[j][0] = __expf(sc[j][0] - mx0);
            sc[j][1] = __expf(sc[j][1] - mx0);
            sc[j][2] = __expf(sc[j][2] - mx1);
            sc[j][3] = __expf(sc[j][3] - mx1);
            s0 += sc[j][0] + sc[j][1];
            s1 += sc[j][2] + sc[j][3];
        }
        s0 += __shfl_xor_sync(0xffffffffu, s0, 1);
        s0 += __shfl_xor_sync(0xffffffffu, s0, 2);
        s1 += __shfl_xor_sync(0xffffffffu, s1, 1);
        s1 += __shfl_xor_sync(0xffffffffu, s1, 2);
        float inv0 = 1.f / s0;
        float inv1 = 1.f / s1;

        uint32_t pf[8][2];
        #pragma unroll
        for (int j = 0; j < 8; j++) {
            pf[j][0] = h2_as_u32(__floats2half2_rn(sc[j][0] * inv0, sc[j][1] * inv0));
            pf[j][1] = h2_as_u32(__floats2half2_rn(sc[j][2] * inv1, sc[j][3] * inv1));
        }

        // O = P @ V
        float oc[8][4];
        #pragma unroll
        for (int j = 0; j < 8; j++)
            #pragma unroll
            for (int q = 0; q < 4; q++) oc[j][q] = 0.f;

        #pragma unroll
        for (int kk2 = 0; kk2 < 4; kk2++) {
            uint32_t a2[4] = { pf[2 * kk2][0], pf[2 * kk2][1], pf[2 * kk2 + 1][0], pf[2 * kk2 + 1][1] };
            uint32_t vf[8][2];
            #pragma unroll
            for (int dj2 = 0; dj2 < 4; dj2++) {
                int mi = lane >> 3, r = lane & 7;
                uint32_t vad = bV + (uint32_t)((kk2 * 16 + (mi & 1) * 8 + r) * QKV_STR + dj2 * 16 + (mi >> 1) * 8) * 2;
                uint32_t r0, r1, r2, r3;
                ldsm_x4t(r0, r1, r2, r3, vad);
                vf[2 * dj2][0] = r0;     vf[2 * dj2][1] = r1;
                vf[2 * dj2 + 1][0] = r2; vf[2 * dj2 + 1][1] = r3;
            }
            #pragma unroll
            for (int j = 0; j < 8; j++) mma_16816(oc[j], a2, vf[j]);
        }

        // ---- stage O into the (now dead) Q region of the CURRENT buffer (warp-local rows) ----
        #pragma unroll
        for (int j = 0; j < 8; j++) {
            int d = j * 8 + 2 * (lane & 3);
            uint32_t a0 = bQ + (uint32_t)(q0 * QKV_STR + d) * 2;
            uint32_t a1 = bQ + (uint32_t)(q1 * QKV_STR + d) * 2;
            uint32_t h0 = h2_as_u32(__floats2half2_rn(oc[j][0], oc[j][1]));
            uint32_t h1 = h2_as_u32(__floats2half2_rn(oc[j][2], oc[j][3]));
            asm volatile("st.shared.b32 [%0], %1;" :: "r"(a0), "r"(h0) : "memory");
            asm volatile("st.shared.b32 [%0], %1;" :: "r"(a1), "r"(h1) : "memory");
        }
        __syncwarp();
        // coalesced write-out: 4 x STG.128, each instr covers 4 full 128B rows
        #pragma unroll
        for (int ii = 0; ii < 4; ii++) {
            int c = ii * 32 + lane;          // 0..127 chunk id within warp tile
            int r = c >> 3;                  // local row 0..15
            int c16 = c & 7;                 // 16B chunk within row
            uint32_t sa = bQ + (uint32_t)((m0 + r) * QKV_STR) * 2 + c16 * 16;
            uint4 val;
            asm volatile("ld.shared.v4.b32 {%0,%1,%2,%3}, [%4];"
                         : "=r"(val.x), "=r"(val.y), "=r"(val.z), "=r"(val.w) : "r"(sa));
            size_t go = ((size_t)b * SEQ + m0 + r) * CH + h * DHD + c16 * 8;
            *(uint4*)(g_o + go) = val;
        }

        __syncthreads();   // all reads of `buf` done before it is refilled next iteration
        buf ^= 1;
    }
}

// ---------------- launch ----------------
extern "C" void kernel_launch(void* const* d_in, const int* in_sizes, int n_in,
                              void* d_out, int out_size)
{
    (void)in_sizes; (void)n_in; (void)out_size;
    const float* x    = (const float*)d_in[0];
    const float* wqkv = (const float*)d_in[1];
    const float* wout = (const float*)d_in[2];
    const float* bvec = (const float*)d_in[3];
    const float* rel  = (const float*)d_in[4];
    float* out = (float*)d_out;

    cudaFuncSetAttribute(gemm_hmma<0>, cudaFuncAttributeMaxDynamicSharedMemorySize, SMEM_DYN);
    cudaFuncSetAttribute(gemm_hmma<1>, cudaFuncAttributeMaxDynamicSharedMemorySize, SMEM_DYN);
    cudaFuncSetAttribute(attn_kernel, cudaFuncAttributeMaxDynamicSharedMemorySize, ATT_SMEM);

    conv_all<<<8192, 256>>>(x, wqkv, wout, rel);

    gemm_hmma<0><<<dim3(NQKV / BN, MROWS / BM), GT, SMEM_DYN>>>(nullptr, nullptr);
    attn_kernel<<<ATT_G, 128, ATT_SMEM>>>();
    gemm_hmma<1><<<dim3(CH / BN, MROWS / BM), GT, SMEM_DYN>>>(bvec, out);
}